// round 1
// baseline (speedup 1.0000x reference)
#include <cuda_runtime.h>
#include <math.h>

#define N_Q   10
#define NB    10
#define DIM   1024          // 1 << N_Q
#define P     128
#define FEAT  (NB * N_Q)    // 100

// ---------------- scratch (device globals: allocation-free) ----------------
__device__ float2 g_psi[P * DIM];     // 1 MB: prepared states
__device__ float  g_part[64 * 2];     // per-tile partial sums (pol, k2)

// ---------------------------------------------------------------------------
// Kernel 1: prepare psi_i = U(data_i)|0> for all 128 points.
// One block per point, 512 threads, state (1024 complex64) in shared memory.
// ---------------------------------------------------------------------------
__global__ __launch_bounds__(512, 1)
void prep_kernel(const float* __restrict__ data,
                 const float* __restrict__ params)
{
    __shared__ float2 s[DIM];
    __shared__ float  th[N_Q];               // per-block RZ angles (data)
    __shared__ float  ryc[NB][N_Q], rys[NB][N_Q];
    __shared__ float  crz[NB][N_Q];

    const int t  = threadIdx.x;              // 0..511
    const int pt = blockIdx.x;               // data point index

    // precompute RY cos/sin tables and CRZ angles (shared trainable params)
    if (t < NB * N_Q) {
        int b = t / N_Q, q = t % N_Q;
        float a0 = params[(b * 2 + 0) * N_Q + q];
        ryc[b][q] = cosf(0.5f * a0);
        rys[b][q] = sinf(0.5f * a0);
        crz[b][q] = params[(b * 2 + 1) * N_Q + q];
    }

    // |0...0>
    s[t]       = make_float2(t == 0 ? 1.0f : 0.0f, 0.0f);
    s[t + 512] = make_float2(0.0f, 0.0f);
    __syncthreads();

    const float INV_S2 = 0.70710678118654752440f;

    for (int blk = 0; blk < NB; blk++) {
        // ---- H layer: butterfly per qubit (MSB-first: qubit q has stride 1<<(9-q))
        #pragma unroll
        for (int q = 0; q < N_Q; q++) {
            const int mask = 1 << (N_Q - 1 - q);
            const int lo   = t & (mask - 1);
            const int i0   = ((t ^ lo) << 1) | lo;
            const int i1   = i0 | mask;
            float2 a = s[i0], b = s[i1];
            s[i0] = make_float2((a.x + b.x) * INV_S2, (a.y + b.y) * INV_S2);
            s[i1] = make_float2((a.x - b.x) * INV_S2, (a.y - b.y) * INV_S2);
            __syncthreads();
        }

        // ---- load per-point RZ angles for this block
        if (t < N_Q) th[t] = data[pt * FEAT + blk * N_Q + t];
        __syncthreads();

        // ---- RZ diagonal: amp_d *= exp(i * sum_q (bit_dq - 0.5) * th_q)
        #pragma unroll
        for (int h = 0; h < 2; h++) {
            const int d = t + h * 512;
            float ang = 0.0f;
            #pragma unroll
            for (int q = 0; q < N_Q; q++) {
                float sgn = ((d >> (N_Q - 1 - q)) & 1) ? 0.5f : -0.5f;
                ang += sgn * th[q];
            }
            float sn, cs;
            sincosf(ang, &sn, &cs);
            float2 a = s[d];
            s[d] = make_float2(a.x * cs - a.y * sn, a.x * sn + a.y * cs);
        }
        __syncthreads();

        // ---- RY layer: butterfly per qubit with [[c,-s],[s,c]]
        #pragma unroll
        for (int q = 0; q < N_Q; q++) {
            const int mask = 1 << (N_Q - 1 - q);
            const int lo   = t & (mask - 1);
            const int i0   = ((t ^ lo) << 1) | lo;
            const int i1   = i0 | mask;
            const float c  = ryc[blk][q];
            const float sv = rys[blk][q];
            float2 a = s[i0], b = s[i1];
            s[i0] = make_float2(c * a.x - sv * b.x, c * a.y - sv * b.y);
            s[i1] = make_float2(sv * a.x + c * b.x, sv * a.y + c * b.y);
            __syncthreads();
        }

        // ---- CRZ ring diagonal: amp_d *= exp(i * sum_q s_q (s_{q+1}-0.5) th_q)
        #pragma unroll
        for (int h = 0; h < 2; h++) {
            const int d = t + h * 512;
            float ang = 0.0f;
            #pragma unroll
            for (int q = 0; q < N_Q; q++) {
                int sq  = (d >> (N_Q - 1 - q)) & 1;
                int sq1 = (d >> (N_Q - 1 - ((q + 1) % N_Q))) & 1;
                if (sq) ang += (sq1 ? 0.5f : -0.5f) * crz[blk][q];
            }
            float sn, cs;
            sincosf(ang, &sn, &cs);
            float2 a = s[d];
            s[d] = make_float2(a.x * cs - a.y * sn, a.x * sn + a.y * cs);
        }
        __syncthreads();
    }

    // write out
    g_psi[pt * DIM + t]       = s[t];
    g_psi[pt * DIM + t + 512] = s[t + 512];
}

// ---------------------------------------------------------------------------
// Kernel 2: Gram matrix tiles. K[i,j] = |<psi_j|psi_i>|^2.
// 64 blocks of 256 threads; block b = 16x16 tile (bi = b>>3, bj = b&7).
// Each block reduces sum(l_i l_j K) and sum(K^2) -> g_part[b].
// ---------------------------------------------------------------------------
#define CHUNK 32

__global__ __launch_bounds__(256, 4)
void gram_kernel(const float* __restrict__ labels)
{
    __shared__ float2 si[16][CHUNK + 1];   // +1 float2 pad kills bank conflicts
    __shared__ float2 sj[16][CHUNK + 1];
    __shared__ float  red1[8], red2[8];

    const int b  = blockIdx.x;
    const int bi = b >> 3;
    const int bj = b & 7;
    const int tx = threadIdx.x & 15;       // j within tile
    const int ty = threadIdx.x >> 4;       // i within tile

    float re = 0.0f, im = 0.0f;

    for (int d0 = 0; d0 < DIM; d0 += CHUNK) {
        __syncthreads();
        #pragma unroll
        for (int k = threadIdx.x; k < 16 * CHUNK; k += 256) {
            int r = k >> 5, c = k & (CHUNK - 1);
            si[r][c] = g_psi[(bi * 16 + r) * DIM + d0 + c];
            sj[r][c] = g_psi[(bj * 16 + r) * DIM + d0 + c];
        }
        __syncthreads();
        #pragma unroll
        for (int c = 0; c < CHUNK; c++) {
            float2 a = si[ty][c];          // psi_i[d]
            float2 bb = sj[tx][c];         // psi_j[d]
            // conj(psi_j) * psi_i
            re += bb.x * a.x + bb.y * a.y;
            im += bb.x * a.y - bb.y * a.x;
        }
    }

    const float K  = re * re + im * im;
    const float li = labels[bi * 16 + ty];
    const float lj = labels[bj * 16 + tx];
    float v1 = li * lj * K;
    float v2 = K * K;

    // block reduce (8 warps)
    #pragma unroll
    for (int o = 16; o; o >>= 1) {
        v1 += __shfl_down_sync(0xffffffffu, v1, o);
        v2 += __shfl_down_sync(0xffffffffu, v2, o);
    }
    const int warp = threadIdx.x >> 5;
    const int lane = threadIdx.x & 31;
    if (lane == 0) { red1[warp] = v1; red2[warp] = v2; }
    __syncthreads();
    if (threadIdx.x < 8) {
        v1 = red1[threadIdx.x];
        v2 = red2[threadIdx.x];
        #pragma unroll
        for (int o = 4; o; o >>= 1) {
            v1 += __shfl_down_sync(0xffu, v1, o);
            v2 += __shfl_down_sync(0xffu, v2, o);
        }
        if (threadIdx.x == 0) {
            g_part[b * 2 + 0] = v1;
            g_part[b * 2 + 1] = v2;
        }
    }
}

// ---------------------------------------------------------------------------
// Kernel 3: final scalar.  out = pol / (sqrt(k2) * sum(l^2))
//   (sum_ij (l_i l_j)^2 == (sum_i l_i^2)^2)
// ---------------------------------------------------------------------------
__global__ void final_kernel(const float* __restrict__ labels,
                             float* __restrict__ out)
{
    __shared__ float sp[4], sk[4], sl[4];
    const int t = threadIdx.x;              // 128 threads

    float pol = 0.0f, k2 = 0.0f;
    if (t < 64) { pol = g_part[2 * t]; k2 = g_part[2 * t + 1]; }
    float l  = labels[t];
    float l2 = l * l;

    #pragma unroll
    for (int o = 16; o; o >>= 1) {
        pol += __shfl_down_sync(0xffffffffu, pol, o);
        k2  += __shfl_down_sync(0xffffffffu, k2, o);
        l2  += __shfl_down_sync(0xffffffffu, l2, o);
    }
    const int warp = t >> 5, lane = t & 31;
    if (lane == 0) { sp[warp] = pol; sk[warp] = k2; sl[warp] = l2; }
    __syncthreads();
    if (t == 0) {
        float POL = sp[0] + sp[1] + sp[2] + sp[3];
        float K2  = sk[0] + sk[1] + sk[2] + sk[3];
        float SL  = sl[0] + sl[1] + sl[2] + sl[3];
        out[0] = POL / (sqrtf(K2) * SL);
    }
}

// ---------------------------------------------------------------------------
extern "C" void kernel_launch(void* const* d_in, const int* in_sizes, int n_in,
                              void* d_out, int out_size)
{
    const float* data   = (const float*)d_in[0];   // [128, 100]
    const float* labels = (const float*)d_in[1];   // [128]
    const float* params = (const float*)d_in[2];   // [10, 2, 10]
    float* out = (float*)d_out;

    prep_kernel <<<P, 512>>>(data, params);
    gram_kernel <<<64, 256>>>(labels);
    final_kernel<<<1, 128>>>(labels, out);
}

// round 3
// speedup vs baseline: 1.5657x; 1.5657x over previous
#include <cuda_runtime.h>
#include <math.h>

#define N_Q   10
#define NB    10
#define DIM   1024
#define P     128
#define FEAT  (NB * N_Q)

typedef unsigned long long ull;

// ---------------- scratch (device globals) ----------------
__device__ float4 g_psiT[DIM * (P / 2)];   // transposed: row d holds 128 complex (64 float4)
__device__ float4 g_psiR[P * (DIM / 2)];   // row-major: point i, 512 float4 (pairs of complex)
__device__ float  g_part[64 * 2];

// packed f32x2 helpers ------------------------------------------------------
__device__ __forceinline__ ull pk(float lo, float hi) {
    ull r; asm("mov.b64 %0, {%1,%2};" : "=l"(r) : "f"(lo), "f"(hi)); return r;
}
__device__ __forceinline__ void fma2(ull& acc, ull a, ull b) {
    asm("fma.rn.f32x2 %0, %1, %2, %0;" : "+l"(acc) : "l"(a), "l"(b));
}
__device__ __forceinline__ void add2(ull& acc, ull v) {
    asm("add.rn.f32x2 %0, %0, %1;" : "+l"(acc) : "l"(v));
}
__device__ __forceinline__ void upk(ull v, float& lo, float& hi) {
    asm("mov.b64 {%0,%1}, %2;" : "=f"(lo), "=f"(hi) : "l"(v));
}

// ---------------------------------------------------------------------------
// Kernel 1: prepare psi_i. State lives in registers: thread t holds d0=2t, d1=2t+1.
// Qubit bitpos p (in d): p=0 -> register-local; p=1..5 -> lane shuffles;
// p=6..9 -> smem float4 exchange (ping-pong buffers, 1 sync each).
// ---------------------------------------------------------------------------
__global__ __launch_bounds__(512, 1)
void prep_kernel(const float* __restrict__ data,
                 const float* __restrict__ params)
{
    __shared__ float4 xb[2][512];
    __shared__ float  ryc[NB * N_Q], rys[NB * N_Q], crz[NB * N_Q];

    const int t    = threadIdx.x;
    const int pt   = blockIdx.x;
    const int lane = t & 31;
    const int d0   = t * 2;
    const int d1   = d0 + 1;
    const float R2 = 0.70710678118654752440f;

    if (t < NB * N_Q) {
        int b = t / N_Q, q = t % N_Q;
        float a = params[(b * 2 + 0) * N_Q + q];
        float sn, cs; __sincosf(0.5f * a, &sn, &cs);
        ryc[t] = cs; rys[t] = sn;
        crz[t] = params[(b * 2 + 1) * N_Q + q];
    }

    float2 a0 = make_float2(t == 0 ? 1.0f : 0.0f, 0.0f);
    float2 a1 = make_float2(0.0f, 0.0f);
    __syncthreads();

    int pb = 0;

    for (int blk = 0; blk < NB; blk++) {
        // prefetch per-point RZ angles for this block (broadcast loads)
        float th[N_Q];
        #pragma unroll
        for (int q = 0; q < N_Q; q++)
            th[q] = __ldg(&data[pt * FEAT + blk * N_Q + q]);

        // ================= H layer =================
        {   // bitpos 0 (register-local)
            float2 n0 = make_float2((a0.x + a1.x) * R2, (a0.y + a1.y) * R2);
            float2 n1 = make_float2((a0.x - a1.x) * R2, (a0.y - a1.y) * R2);
            a0 = n0; a1 = n1;
        }
        #pragma unroll
        for (int k = 0; k < 5; k++) {          // bitpos 1..5 -> lane bits 0..4
            int m = 1 << k;
            float b0x = __shfl_xor_sync(0xffffffffu, a0.x, m);
            float b0y = __shfl_xor_sync(0xffffffffu, a0.y, m);
            float b1x = __shfl_xor_sync(0xffffffffu, a1.x, m);
            float b1y = __shfl_xor_sync(0xffffffffu, a1.y, m);
            float sg  = (lane & m) ? -1.0f : 1.0f;
            a0.x = (b0x + sg * a0.x) * R2; a0.y = (b0y + sg * a0.y) * R2;
            a1.x = (b1x + sg * a1.x) * R2; a1.y = (b1y + sg * a1.y) * R2;
        }
        #pragma unroll
        for (int k = 0; k < 4; k++) {          // bitpos 6..9 -> thread bits 5..8
            int M = 32 << k;
            xb[pb][t] = make_float4(a0.x, a0.y, a1.x, a1.y);
            __syncthreads();
            float4 v = xb[pb][t ^ M];
            pb ^= 1;
            float sg = (t & M) ? -1.0f : 1.0f;
            a0.x = (v.x + sg * a0.x) * R2; a0.y = (v.y + sg * a0.y) * R2;
            a1.x = (v.z + sg * a1.x) * R2; a1.y = (v.w + sg * a1.y) * R2;
        }

        // ================= RZ diagonal =================
        {
            float base = 0.0f;
            #pragma unroll
            for (int q = 0; q < N_Q; q++)
                base += (((d0 >> (N_Q - 1 - q)) & 1) ? 0.5f : -0.5f) * th[q];
            // d1 = d0|1 flips only qubit 9's bit (0 -> 1): delta = th[9]
            float s0, c0, s1, c1;
            __sincosf(base,          &s0, &c0);
            __sincosf(base + th[9],  &s1, &c1);
            float2 n0 = make_float2(a0.x * c0 - a0.y * s0, a0.x * s0 + a0.y * c0);
            float2 n1 = make_float2(a1.x * c1 - a1.y * s1, a1.x * s1 + a1.y * c1);
            a0 = n0; a1 = n1;
        }

        // ================= RY layer =================
        {   // bitpos 0 -> qubit 9
            float c = ryc[blk * N_Q + 9], s = rys[blk * N_Q + 9];
            float2 n0 = make_float2(c * a0.x - s * a1.x, c * a0.y - s * a1.y);
            float2 n1 = make_float2(s * a0.x + c * a1.x, s * a0.y + c * a1.y);
            a0 = n0; a1 = n1;
        }
        #pragma unroll
        for (int k = 0; k < 5; k++) {          // bitpos k+1 -> qubit 8-k
            int m = 1 << k;
            float c = ryc[blk * N_Q + (8 - k)], s = rys[blk * N_Q + (8 - k)];
            float b0x = __shfl_xor_sync(0xffffffffu, a0.x, m);
            float b0y = __shfl_xor_sync(0xffffffffu, a0.y, m);
            float b1x = __shfl_xor_sync(0xffffffffu, a1.x, m);
            float b1y = __shfl_xor_sync(0xffffffffu, a1.y, m);
            float sg  = (lane & m) ? s : -s;   // lo: c*a - s*b ; hi: c*a + s*b
            a0.x = c * a0.x + sg * b0x; a0.y = c * a0.y + sg * b0y;
            a1.x = c * a1.x + sg * b1x; a1.y = c * a1.y + sg * b1y;
        }
        #pragma unroll
        for (int k = 0; k < 4; k++) {          // bitpos 6+k -> qubit 3-k
            int M = 32 << k;
            float c = ryc[blk * N_Q + (3 - k)], s = rys[blk * N_Q + (3 - k)];
            xb[pb][t] = make_float4(a0.x, a0.y, a1.x, a1.y);
            __syncthreads();
            float4 v = xb[pb][t ^ M];
            pb ^= 1;
            float sg = (t & M) ? s : -s;
            a0.x = c * a0.x + sg * v.x; a0.y = c * a0.y + sg * v.y;
            a1.x = c * a1.x + sg * v.z; a1.y = c * a1.y + sg * v.w;
        }

        // ================= CRZ-ring diagonal =================
        {
            float ang0 = 0.0f, ang1 = 0.0f;
            #pragma unroll
            for (int q = 0; q < N_Q; q++) {
                int pA = N_Q - 1 - q;
                int pB = (q == N_Q - 1) ? (N_Q - 1) : (N_Q - 2 - q);
                float cz = crz[blk * N_Q + q];
                if ((d0 >> pA) & 1) ang0 += (((d0 >> pB) & 1) ? 0.5f : -0.5f) * cz;
                if ((d1 >> pA) & 1) ang1 += (((d1 >> pB) & 1) ? 0.5f : -0.5f) * cz;
            }
            float s0, c0, s1, c1;
            __sincosf(ang0, &s0, &c0);
            __sincosf(ang1, &s1, &c1);
            float2 n0 = make_float2(a0.x * c0 - a0.y * s0, a0.x * s0 + a0.y * c0);
            float2 n1 = make_float2(a1.x * c1 - a1.y * s1, a1.x * s1 + a1.y * c1);
            a0 = n0; a1 = n1;
        }
    }

    // write out: transposed [d][i] and row-major pairs [i][dp]
    float2* psiT2 = (float2*)g_psiT;
    psiT2[d0 * P + pt] = a0;
    psiT2[d1 * P + pt] = a1;
    g_psiR[pt * (DIM / 2) + t] = make_float4(a0.x, a0.y, a1.x, a1.y);
}

// ---------------------------------------------------------------------------
// Kernel 2: Gram. 64 blocks x 256 threads. Block bi owns i in {2bi, 2bi+1}.
// Thread: jt = tid&63 (j-pair 2jt,2jt+1), ks = tid>>6 (split-K over d).
// Inner loop: packed f32x2 complex MACs, all operands from L2 (no smem).
// ---------------------------------------------------------------------------
__global__ __launch_bounds__(256, 2)
void gram_kernel(const float* __restrict__ labels)
{
    __shared__ ull sbuf[256 * 8];          // 16 KB partial accumulators
    __shared__ float red1[8], red2[8];

    const int tid = threadIdx.x;
    const int jt  = tid & 63;
    const int ks  = tid >> 6;
    const int bi  = blockIdx.x;
    const int i0  = bi * 2;

    const float4* __restrict__ BT = g_psiT;                  // row d: 64 float4
    const float4* __restrict__ A0 = &g_psiR[i0 * (DIM / 2)];
    const float4* __restrict__ A1 = &g_psiR[(i0 + 1) * (DIM / 2)];

    ull accp[2][2] = {{0ull, 0ull}, {0ull, 0ull}};   // [i][j]: (Sum ax*bx, Sum ay*by)
    ull accm[2][2] = {{0ull, 0ull}, {0ull, 0ull}};   // [i][j]: (Sum ax*by, Sum ay*bx)

    const int dp0 = ks * 128;
    #pragma unroll 4
    for (int dp = dp0; dp < dp0 + 128; dp++) {
        const int d = dp * 2;
        float4 B0 = __ldg(&BT[d * 64 + jt]);         // row d,  j pair
        float4 B1 = __ldg(&BT[(d + 1) * 64 + jt]);   // row d+1
        float4 Aa = __ldg(&A0[dp]);                  // psi_i0 at d, d+1
        float4 Ab = __ldg(&A1[dp]);                  // psi_i1 at d, d+1

        ull a[2][2];                                 // [i][dd]
        a[0][0] = pk(Aa.x, Aa.y); a[0][1] = pk(Aa.z, Aa.w);
        a[1][0] = pk(Ab.x, Ab.y); a[1][1] = pk(Ab.z, Ab.w);
        ull b[2][2], s[2][2];                        // [j][dd]
        b[0][0] = pk(B0.x, B0.y); b[1][0] = pk(B0.z, B0.w);
        b[0][1] = pk(B1.x, B1.y); b[1][1] = pk(B1.z, B1.w);
        s[0][0] = pk(B0.y, B0.x); s[1][0] = pk(B0.w, B0.z);
        s[0][1] = pk(B1.y, B1.x); s[1][1] = pk(B1.w, B1.z);

        #pragma unroll
        for (int dd = 0; dd < 2; dd++)
            #pragma unroll
            for (int i = 0; i < 2; i++)
                #pragma unroll
                for (int j = 0; j < 2; j++) {
                    fma2(accp[i][j], a[i][dd], b[j][dd]);
                    fma2(accm[i][j], a[i][dd], s[j][dd]);
                }
    }

    // stash partials, combine across split-K groups (fixed order: deterministic)
    ull* mine = &sbuf[tid * 8];
    #pragma unroll
    for (int i = 0; i < 2; i++)
        #pragma unroll
        for (int j = 0; j < 2; j++) {
            mine[(i * 2 + j) * 2 + 0] = accp[i][j];
            mine[(i * 2 + j) * 2 + 1] = accm[i][j];
        }
    __syncthreads();

    float v1 = 0.0f, v2 = 0.0f;
    if (ks == 0) {
        #pragma unroll
        for (int g = 1; g < 4; g++) {
            ull* o = &sbuf[(g * 64 + jt) * 8];
            #pragma unroll
            for (int i = 0; i < 2; i++)
                #pragma unroll
                for (int j = 0; j < 2; j++) {
                    add2(accp[i][j], o[(i * 2 + j) * 2 + 0]);
                    add2(accm[i][j], o[(i * 2 + j) * 2 + 1]);
                }
        }
        float li[2] = { labels[i0], labels[i0 + 1] };
        float lj[2] = { labels[2 * jt], labels[2 * jt + 1] };
        #pragma unroll
        for (int i = 0; i < 2; i++)
            #pragma unroll
            for (int j = 0; j < 2; j++) {
                float pxx, pyy, mxy, myx;
                upk(accp[i][j], pxx, pyy);
                upk(accm[i][j], mxy, myx);
                float re = pxx + pyy;
                float im = mxy - myx;
                float K  = re * re + im * im;
                v1 += li[i] * lj[j] * K;
                v2 += K * K;
            }
    }

    // block reduction (threads with ks!=0 contribute zeros)
    #pragma unroll
    for (int o = 16; o; o >>= 1) {
        v1 += __shfl_down_sync(0xffffffffu, v1, o);
        v2 += __shfl_down_sync(0xffffffffu, v2, o);
    }
    const int warp = tid >> 5, lanei = tid & 31;
    if (lanei == 0) { red1[warp] = v1; red2[warp] = v2; }
    __syncthreads();
    if (tid < 8) {
        v1 = red1[tid]; v2 = red2[tid];
        #pragma unroll
        for (int o = 4; o; o >>= 1) {
            v1 += __shfl_down_sync(0xffu, v1, o);
            v2 += __shfl_down_sync(0xffu, v2, o);
        }
        if (tid == 0) {
            g_part[bi * 2 + 0] = v1;
            g_part[bi * 2 + 1] = v2;
        }
    }
}

// ---------------------------------------------------------------------------
// Kernel 3: final scalar.  out = pol / (sqrt(k2) * sum(l^2))
// ---------------------------------------------------------------------------
__global__ void final_kernel(const float* __restrict__ labels,
                             float* __restrict__ out)
{
    __shared__ float sp[4], sk[4], sl[4];
    const int t = threadIdx.x;   // 128 threads

    float pol = 0.0f, k2 = 0.0f;
    if (t < 64) { pol = g_part[2 * t]; k2 = g_part[2 * t + 1]; }
    float l  = labels[t];
    float l2 = l * l;

    #pragma unroll
    for (int o = 16; o; o >>= 1) {
        pol += __shfl_down_sync(0xffffffffu, pol, o);
        k2  += __shfl_down_sync(0xffffffffu, k2, o);
        l2  += __shfl_down_sync(0xffffffffu, l2, o);
    }
    const int warp = t >> 5, lane = t & 31;
    if (lane == 0) { sp[warp] = pol; sk[warp] = k2; sl[warp] = l2; }
    __syncthreads();
    if (t == 0) {
        float POL = sp[0] + sp[1] + sp[2] + sp[3];
        float K2  = sk[0] + sk[1] + sk[2] + sk[3];
        float SL  = sl[0] + sl[1] + sl[2] + sl[3];
        out[0] = POL / (sqrtf(K2) * SL);
    }
}

// ---------------------------------------------------------------------------
extern "C" void kernel_launch(void* const* d_in, const int* in_sizes, int n_in,
                              void* d_out, int out_size)
{
    const float* data   = (const float*)d_in[0];   // [128, 100]
    const float* labels = (const float*)d_in[1];   // [128]
    const float* params = (const float*)d_in[2];   // [10, 2, 10]
    float* out = (float*)d_out;

    prep_kernel <<<P, 512>>>(data, params);
    gram_kernel <<<64, 256>>>(labels);
    final_kernel<<<1, 128>>>(labels, out);
}

// round 5
// speedup vs baseline: 1.7600x; 1.1241x over previous
#include <cuda_runtime.h>
#include <math.h>

#define N_Q   10
#define NB    10
#define DIM   1024
#define P     128
#define FEAT  (NB * N_Q)
#define G     16              // 8-row groups
#define NTILE 136             // G*(G+1)/2 triangular tiles

typedef unsigned long long ull;

// ---------------- scratch (device globals) ----------------
__device__ float4 g_psiT4[(DIM / 2) * P];  // [dp][pt]: dims (2dp,2dp+1) of point pt
__device__ float  g_part[NTILE * 2];

// packed f32x2 helpers ------------------------------------------------------
__device__ __forceinline__ ull pk(float lo, float hi) {
    ull r; asm("mov.b64 %0, {%1,%2};" : "=l"(r) : "f"(lo), "f"(hi)); return r;
}
__device__ __forceinline__ void upk(ull v, float& lo, float& hi) {
    asm("mov.b64 {%0,%1}, %2;" : "=f"(lo), "=f"(hi) : "l"(v));
}
__device__ __forceinline__ ull mul2_(ull a, ull b) {
    ull r; asm("mul.rn.f32x2 %0,%1,%2;" : "=l"(r) : "l"(a), "l"(b)); return r;
}
__device__ __forceinline__ ull fma2_(ull a, ull b, ull c) {
    ull r; asm("fma.rn.f32x2 %0,%1,%2,%3;" : "=l"(r) : "l"(a), "l"(b), "l"(c)); return r;
}
__device__ __forceinline__ void fma2acc(ull& acc, ull a, ull b) {
    asm("fma.rn.f32x2 %0, %1, %2, %0;" : "+l"(acc) : "l"(a), "l"(b));
}
__device__ __forceinline__ void add2acc(ull& acc, ull v) {
    asm("add.rn.f32x2 %0, %0, %1;" : "+l"(acc) : "l"(v));
}

// ---------------------------------------------------------------------------
// Kernel 1: prepare psi_i. Thread t holds d0=2t, d1=2t+1 in registers.
// Butterfly arithmetic in packed f32x2.
// ---------------------------------------------------------------------------
__global__ __launch_bounds__(512, 1)
void prep_kernel(const float* __restrict__ data,
                 const float* __restrict__ params)
{
    __shared__ float4 xb[2][512];
    __shared__ float  ryc[NB * N_Q], rys[NB * N_Q], crz[NB * N_Q];

    const int t    = threadIdx.x;
    const int pt   = blockIdx.x;
    const int lane = t & 31;
    const int d0   = t * 2;
    const int d1   = d0 + 1;
    const float R2 = 0.70710678118654752440f;
    const ull  r2p = pk(R2, R2);

    if (t < NB * N_Q) {
        int b = t / N_Q, q = t % N_Q;
        float a = params[(b * 2 + 0) * N_Q + q];
        float sn, cs; __sincosf(0.5f * a, &sn, &cs);
        ryc[t] = cs; rys[t] = sn;
        crz[t] = params[(b * 2 + 1) * N_Q + q];
    }

    float2 a0 = make_float2(t == 0 ? 1.0f : 0.0f, 0.0f);
    float2 a1 = make_float2(0.0f, 0.0f);
    __syncthreads();

    int pb = 0;

    for (int blk = 0; blk < NB; blk++) {
        float th[N_Q];
        #pragma unroll
        for (int q = 0; q < N_Q; q++)
            th[q] = __ldg(&data[pt * FEAT + blk * N_Q + q]);

        // ================= H layer =================
        {   // bitpos 0 (register-local): n0=(a0+a1)*R2, n1=(a0-a1)*R2
            ull p0 = pk(a0.x, a0.y), p1 = pk(a1.x, a1.y);
            ull tt = mul2_(p0, r2p);
            ull n0 = fma2_(p1, r2p, tt);
            ull n1 = fma2_(p1, pk(-R2, -R2), tt);
            upk(n0, a0.x, a0.y); upk(n1, a1.x, a1.y);
        }
        #pragma unroll
        for (int k = 0; k < 5; k++) {          // bitpos 1..5 -> lane bits
            int m = 1 << k;
            float b0x = __shfl_xor_sync(0xffffffffu, a0.x, m);
            float b0y = __shfl_xor_sync(0xffffffffu, a0.y, m);
            float b1x = __shfl_xor_sync(0xffffffffu, a1.x, m);
            float b1y = __shfl_xor_sync(0xffffffffu, a1.y, m);
            float sg  = (lane & m) ? -R2 : R2;
            ull sgp = pk(sg, sg);
            ull n0 = fma2_(pk(a0.x, a0.y), sgp, mul2_(pk(b0x, b0y), r2p));
            ull n1 = fma2_(pk(a1.x, a1.y), sgp, mul2_(pk(b1x, b1y), r2p));
            upk(n0, a0.x, a0.y); upk(n1, a1.x, a1.y);
        }
        #pragma unroll
        for (int k = 0; k < 4; k++) {          // bitpos 6..9 -> thread bits 5..8
            int M = 32 << k;
            xb[pb][t] = make_float4(a0.x, a0.y, a1.x, a1.y);
            __syncthreads();
            float4 v = xb[pb][t ^ M];
            pb ^= 1;
            float sg = (t & M) ? -R2 : R2;
            ull sgp = pk(sg, sg);
            ull n0 = fma2_(pk(a0.x, a0.y), sgp, mul2_(pk(v.x, v.y), r2p));
            ull n1 = fma2_(pk(a1.x, a1.y), sgp, mul2_(pk(v.z, v.w), r2p));
            upk(n0, a0.x, a0.y); upk(n1, a1.x, a1.y);
        }

        // ================= RZ diagonal =================
        {
            float base = 0.0f;
            #pragma unroll
            for (int q = 0; q < N_Q; q++)
                base += (((d0 >> (N_Q - 1 - q)) & 1) ? 0.5f : -0.5f) * th[q];
            float s0, c0, s1, c1;
            __sincosf(base,         &s0, &c0);
            __sincosf(base + th[9], &s1, &c1);
            float2 n0 = make_float2(a0.x * c0 - a0.y * s0, a0.x * s0 + a0.y * c0);
            float2 n1 = make_float2(a1.x * c1 - a1.y * s1, a1.x * s1 + a1.y * c1);
            a0 = n0; a1 = n1;
        }

        // ================= RY layer =================
        {   // bitpos 0 -> qubit 9: n0 = c*a0 - s*a1 ; n1 = s*a0 + c*a1
            float c = ryc[blk * N_Q + 9], s = rys[blk * N_Q + 9];
            ull p0 = pk(a0.x, a0.y), p1 = pk(a1.x, a1.y);
            ull cp = pk(c, c);
            ull n0 = fma2_(p1, pk(-s, -s), mul2_(p0, cp));
            ull n1 = fma2_(p1, cp, mul2_(p0, pk(s, s)));
            upk(n0, a0.x, a0.y); upk(n1, a1.x, a1.y);
        }
        #pragma unroll
        for (int k = 0; k < 5; k++) {          // bitpos k+1 -> qubit 8-k
            int m = 1 << k;
            float c = ryc[blk * N_Q + (8 - k)], s = rys[blk * N_Q + (8 - k)];
            float b0x = __shfl_xor_sync(0xffffffffu, a0.x, m);
            float b0y = __shfl_xor_sync(0xffffffffu, a0.y, m);
            float b1x = __shfl_xor_sync(0xffffffffu, a1.x, m);
            float b1y = __shfl_xor_sync(0xffffffffu, a1.y, m);
            float sg  = (lane & m) ? s : -s;
            ull cp = pk(c, c), sgp = pk(sg, sg);
            ull n0 = fma2_(pk(b0x, b0y), sgp, mul2_(pk(a0.x, a0.y), cp));
            ull n1 = fma2_(pk(b1x, b1y), sgp, mul2_(pk(a1.x, a1.y), cp));
            upk(n0, a0.x, a0.y); upk(n1, a1.x, a1.y);
        }
        #pragma unroll
        for (int k = 0; k < 4; k++) {          // bitpos 6+k -> qubit 3-k
            int M = 32 << k;
            float c = ryc[blk * N_Q + (3 - k)], s = rys[blk * N_Q + (3 - k)];
            xb[pb][t] = make_float4(a0.x, a0.y, a1.x, a1.y);
            __syncthreads();
            float4 v = xb[pb][t ^ M];
            pb ^= 1;
            float sg = (t & M) ? s : -s;
            ull cp = pk(c, c), sgp = pk(sg, sg);
            ull n0 = fma2_(pk(v.x, v.y), sgp, mul2_(pk(a0.x, a0.y), cp));
            ull n1 = fma2_(pk(v.z, v.w), sgp, mul2_(pk(a1.x, a1.y), cp));
            upk(n0, a0.x, a0.y); upk(n1, a1.x, a1.y);
        }

        // ================= CRZ-ring diagonal =================
        {
            float ang0 = 0.0f, ang1 = 0.0f;
            #pragma unroll
            for (int q = 0; q < N_Q; q++) {
                int pA = N_Q - 1 - q;
                int pB = (q == N_Q - 1) ? (N_Q - 1) : (N_Q - 2 - q);
                float cz = crz[blk * N_Q + q];
                if ((d0 >> pA) & 1) ang0 += (((d0 >> pB) & 1) ? 0.5f : -0.5f) * cz;
                if ((d1 >> pA) & 1) ang1 += (((d1 >> pB) & 1) ? 0.5f : -0.5f) * cz;
            }
            float s0, c0, s1, c1;
            __sincosf(ang0, &s0, &c0);
            __sincosf(ang1, &s1, &c1);
            float2 n0 = make_float2(a0.x * c0 - a0.y * s0, a0.x * s0 + a0.y * c0);
            float2 n1 = make_float2(a1.x * c1 - a1.y * s1, a1.x * s1 + a1.y * c1);
            a0 = n0; a1 = n1;
        }
    }

    // write out in [dp][pt] layout (dp = t)
    g_psiT4[t * P + pt] = make_float4(a0.x, a0.y, a1.x, a1.y);
}

// ---------------------------------------------------------------------------
// Kernel 2: symmetric Gram. 136 blocks = triangular 8x8-group tiles (I<=J).
// 256 threads = 8 ii x 8 jj x 4 split-K. K[i,i]=1 handled analytically.
// Off-diag pairs weighted 2 (covers (j,i) mirror).
// ---------------------------------------------------------------------------
__global__ __launch_bounds__(256, 1)
void gram_kernel(const float* __restrict__ labels)
{
    __shared__ ull  sbuf[256 * 2];        // per-thread (accp, accm)
    __shared__ float red1[8], red2[8];

    const int tid = threadIdx.x;
    const int ii  = tid & 7;
    const int jj  = (tid >> 3) & 7;
    const int ks  = tid >> 6;

    // triangular decode: block b -> (I, J), I <= J
    int I = 0, rem = blockIdx.x;
    while (rem >= G - I) { rem -= G - I; I++; }
    const int J = I + rem;

    const int i = I * 8 + ii;
    const int j = J * 8 + jj;
    const float w = (I < J) ? 2.0f : ((ii < jj) ? 2.0f : 0.0f);

    ull accp = 0ull;   // (Sum Ax*Bx, Sum Ay*By)
    ull accm = 0ull;   // (Sum Ay*Bx, Sum Ax*By)

    const int dp0 = ks * 128;
    #pragma unroll 4
    for (int dp = dp0; dp < dp0 + 128; dp++) {
        float4 A = __ldg(&g_psiT4[dp * P + i]);   // psi_i dims 2dp, 2dp+1
        float4 B = __ldg(&g_psiT4[dp * P + j]);   // psi_j dims 2dp, 2dp+1
        fma2acc(accp, pk(A.x, A.y), pk(B.x, B.y));
        fma2acc(accm, pk(A.y, A.x), pk(B.x, B.y));
        fma2acc(accp, pk(A.z, A.w), pk(B.z, B.w));
        fma2acc(accm, pk(A.w, A.z), pk(B.z, B.w));
    }

    // combine split-K partials (fixed order -> deterministic)
    sbuf[tid * 2 + 0] = accp;
    sbuf[tid * 2 + 1] = accm;
    __syncthreads();

    float v1 = 0.0f, v2 = 0.0f;
    if (ks == 0) {
        #pragma unroll
        for (int g = 1; g < 4; g++) {
            add2acc(accp, sbuf[(g * 64 + tid) * 2 + 0]);
            add2acc(accm, sbuf[(g * 64 + tid) * 2 + 1]);
        }
        float pxx, pyy, myx, mxy;
        upk(accp, pxx, pyy);       // (AxBx, AyBy)
        upk(accm, myx, mxy);       // (AyBx, AxBy)
        float re = pxx + pyy;      // Re(conj(B) dot A)
        float im = mxy - myx;      // Im: Bx*Ay - By*Ax
        float K  = re * re + im * im;
        v1 = w * labels[i] * labels[j] * K;
        v2 = w * K * K;
    }

    #pragma unroll
    for (int o = 16; o; o >>= 1) {
        v1 += __shfl_down_sync(0xffffffffu, v1, o);
        v2 += __shfl_down_sync(0xffffffffu, v2, o);
    }
    const int warp = tid >> 5, lanei = tid & 31;
    if (lanei == 0) { red1[warp] = v1; red2[warp] = v2; }
    __syncthreads();
    if (tid < 8) {
        v1 = red1[tid]; v2 = red2[tid];
        #pragma unroll
        for (int o = 4; o; o >>= 1) {
            v1 += __shfl_down_sync(0xffu, v1, o);
            v2 += __shfl_down_sync(0xffu, v2, o);
        }
        if (tid == 0) {
            g_part[blockIdx.x * 2 + 0] = v1;
            g_part[blockIdx.x * 2 + 1] = v2;
        }
    }
}

// ---------------------------------------------------------------------------
// Kernel 3: final scalar. Adds analytic diagonal (K[i,i] = 1):
//   pol += sum li^2 ; k2 += P.   out = pol / (sqrt(k2) * sum(l^2))
// ---------------------------------------------------------------------------
__global__ void final_kernel(const float* __restrict__ labels,
                             float* __restrict__ out)
{
    __shared__ float sp[8], sk[8], sl[8];
    const int t = threadIdx.x;              // 256 threads

    float pol = 0.0f, k2 = 0.0f, l2 = 0.0f;
    if (t < NTILE) { pol = g_part[2 * t]; k2 = g_part[2 * t + 1]; }
    if (t < P) {
        float l = labels[t];
        l2 = l * l;
        pol += l2;        // diagonal polarity term
        k2  += 1.0f;      // diagonal K^2 term
    }

    #pragma unroll
    for (int o = 16; o; o >>= 1) {
        pol += __shfl_down_sync(0xffffffffu, pol, o);
        k2  += __shfl_down_sync(0xffffffffu, k2, o);
        l2  += __shfl_down_sync(0xffffffffu, l2, o);
    }
    const int warp = t >> 5, lane = t & 31;
    if (lane == 0) { sp[warp] = pol; sk[warp] = k2; sl[warp] = l2; }
    __syncthreads();
    if (t == 0) {
        float POL = 0.0f, K2 = 0.0f, SL = 0.0f;
        #pragma unroll
        for (int wv = 0; wv < 8; wv++) { POL += sp[wv]; K2 += sk[wv]; SL += sl[wv]; }
        out[0] = POL / (sqrtf(K2) * SL);
    }
}

// ---------------------------------------------------------------------------
extern "C" void kernel_launch(void* const* d_in, const int* in_sizes, int n_in,
                              void* d_out, int out_size)
{
    const float* data   = (const float*)d_in[0];   // [128, 100]
    const float* labels = (const float*)d_in[1];   // [128]
    const float* params = (const float*)d_in[2];   // [10, 2, 10]
    float* out = (float*)d_out;

    prep_kernel <<<P, 512>>>(data, params);
    gram_kernel <<<NTILE, 256>>>(labels);
    final_kernel<<<1, 256>>>(labels, out);
}

// round 6
// speedup vs baseline: 1.8558x; 1.0544x over previous
#include <cuda_runtime.h>
#include <math.h>

#define N_Q   10
#define NB    10
#define DIM   1024
#define P     128
#define FEAT  (NB * N_Q)
#define G     16
#define NTILE 136
#define NBLK  128

typedef unsigned long long ull;

// ---------------- scratch (device globals) ----------------
__device__ float4   g_psiT4[(DIM / 2) * P];  // [dp][pt]
__device__ float    g_part[NTILE * 2];
__device__ unsigned g_bar = 0;               // monotonic grid-barrier counter

// packed f32x2 helpers ------------------------------------------------------
__device__ __forceinline__ ull pk(float lo, float hi) {
    ull r; asm("mov.b64 %0, {%1,%2};" : "=l"(r) : "f"(lo), "f"(hi)); return r;
}
__device__ __forceinline__ void upk(ull v, float& lo, float& hi) {
    asm("mov.b64 {%0,%1}, %2;" : "=f"(lo), "=f"(hi) : "l"(v));
}
__device__ __forceinline__ ull mul2_(ull a, ull b) {
    ull r; asm("mul.rn.f32x2 %0,%1,%2;" : "=l"(r) : "l"(a), "l"(b)); return r;
}
__device__ __forceinline__ ull fma2_(ull a, ull b, ull c) {
    ull r; asm("fma.rn.f32x2 %0,%1,%2,%3;" : "=l"(r) : "l"(a), "l"(b), "l"(c)); return r;
}
__device__ __forceinline__ void fma2acc(ull& acc, ull a, ull b) {
    asm("fma.rn.f32x2 %0, %1, %2, %0;" : "+l"(acc) : "l"(a), "l"(b));
}
__device__ __forceinline__ void add2acc(ull& acc, ull v) {
    asm("add.rn.f32x2 %0, %0, %1;" : "+l"(acc) : "l"(v));
}

// monotonic grid barrier: every call adds NBLK arrivals; never reset -> replay-safe
__device__ __forceinline__ void grid_sync() {
    __syncthreads();
    __threadfence();
    if (threadIdx.x == 0) {
        unsigned old = atomicAdd(&g_bar, 1u);
        unsigned target = (old / NBLK + 1u) * NBLK;
        unsigned cur;
        do {
            asm volatile("ld.acquire.gpu.u32 %0, [%1];" : "=r"(cur) : "l"(&g_bar));
        } while (cur < target);
    }
    __syncthreads();
    __threadfence();
}

// ---------------------------------------------------------------------------
// Fused kernel: prep -> grid_sync -> gram -> grid_sync -> final (block 0)
// ---------------------------------------------------------------------------
__global__ __launch_bounds__(512, 1)
void fused_kernel(const float* __restrict__ data,
                  const float* __restrict__ labels,
                  const float* __restrict__ params,
                  float* __restrict__ out)
{
    __shared__ float4 xb[2][512];            // transpose buffers (ping-pong)
    __shared__ float  ryc[NB * N_Q], rys[NB * N_Q], crz[NB * N_Q];
    __shared__ float  red1[16], red2[16];

    const int t    = threadIdx.x;
    const int pt   = blockIdx.x;
    const int lane = t & 31;
    const float R2 = 0.70710678118654752440f;
    const ull  r2p = pk(R2, R2);

    // ownership-transpose indices: swap t bits [8:5] <-> [3:0], keep bit 4
    const int swp  = (t & 0x10) | ((t & 0xF) << 5) | ((t >> 5) & 0xF);
    const int widx = t   ^ ((t   >> 5) & 0xF);   // swizzled own slot
    const int ridx = swp ^ ((swp >> 5) & 0xF);   // swizzled partner slot
    const int dA0 = 2 * t,   dA1 = dA0 + 1;      // phase-A basis indices
    const int dB0 = 2 * swp, dB1 = dB0 + 1;      // phase-B basis indices

    if (t < NB * N_Q) {
        int b = t / N_Q, q = t % N_Q;
        float a = params[(b * 2 + 0) * N_Q + q];
        float sn, cs; __sincosf(0.5f * a, &sn, &cs);
        ryc[t] = cs; rys[t] = sn;
        crz[t] = params[(b * 2 + 1) * N_Q + q];
    }
    __syncthreads();

    // ====================== PHASE 1: state prep ======================
    float2 a0 = make_float2(0.0f, 0.0f);
    float2 a1 = make_float2(0.0f, 0.0f);

    for (int blk = 0; blk < NB; blk++) {
        float th[N_Q];
        #pragma unroll
        for (int q = 0; q < N_Q; q++)
            th[q] = __ldg(&data[pt * FEAT + blk * N_Q + q]);

        if (blk == 0) {
            // H^{x10}|0...0> = uniform 1/32 (real); start directly in phase B
            a0 = make_float2(0.03125f, 0.0f);
            a1 = make_float2(0.03125f, 0.0f);
        } else {
            // ---- H phase A: bit 0 local + bits 1..5 lane shuffles
            {
                ull p0 = pk(a0.x, a0.y), p1 = pk(a1.x, a1.y);
                ull tt = mul2_(p0, r2p);
                ull n0 = fma2_(p1, r2p, tt);
                ull n1 = fma2_(p1, pk(-R2, -R2), tt);
                upk(n0, a0.x, a0.y); upk(n1, a1.x, a1.y);
            }
            #pragma unroll
            for (int k = 0; k < 5; k++) {
                int m = 1 << k;
                float b0x = __shfl_xor_sync(0xffffffffu, a0.x, m);
                float b0y = __shfl_xor_sync(0xffffffffu, a0.y, m);
                float b1x = __shfl_xor_sync(0xffffffffu, a1.x, m);
                float b1y = __shfl_xor_sync(0xffffffffu, a1.y, m);
                float sg  = (lane & m) ? -R2 : R2;
                ull sgp = pk(sg, sg);
                ull n0 = fma2_(pk(a0.x, a0.y), sgp, mul2_(pk(b0x, b0y), r2p));
                ull n1 = fma2_(pk(a1.x, a1.y), sgp, mul2_(pk(b1x, b1y), r2p));
                upk(n0, a0.x, a0.y); upk(n1, a1.x, a1.y);
            }
            // ---- transpose A -> B
            xb[0][widx] = make_float4(a0.x, a0.y, a1.x, a1.y);
            __syncthreads();
            {
                float4 v = xb[0][ridx];
                a0 = make_float2(v.x, v.y);
                a1 = make_float2(v.z, v.w);
            }
            // ---- H phase B: d-bits 6..9 are now lane bits 0..3
            #pragma unroll
            for (int k = 0; k < 4; k++) {
                int m = 1 << k;
                float b0x = __shfl_xor_sync(0xffffffffu, a0.x, m);
                float b0y = __shfl_xor_sync(0xffffffffu, a0.y, m);
                float b1x = __shfl_xor_sync(0xffffffffu, a1.x, m);
                float b1y = __shfl_xor_sync(0xffffffffu, a1.y, m);
                float sg  = (lane & m) ? -R2 : R2;
                ull sgp = pk(sg, sg);
                ull n0 = fma2_(pk(a0.x, a0.y), sgp, mul2_(pk(b0x, b0y), r2p));
                ull n1 = fma2_(pk(a1.x, a1.y), sgp, mul2_(pk(b1x, b1y), r2p));
                upk(n0, a0.x, a0.y); upk(n1, a1.x, a1.y);
            }
        }

        // ---- RZ diagonal (phase-B ownership; d1 differs only in qubit-9 bit)
        {
            float base = 0.0f;
            #pragma unroll
            for (int q = 0; q < N_Q; q++)
                base += (((dB0 >> (N_Q - 1 - q)) & 1) ? 0.5f : -0.5f) * th[q];
            float s0, c0, s1, c1;
            __sincosf(base,         &s0, &c0);
            __sincosf(base + th[9], &s1, &c1);
            float2 n0 = make_float2(a0.x * c0 - a0.y * s0, a0.x * s0 + a0.y * c0);
            float2 n1 = make_float2(a1.x * c1 - a1.y * s1, a1.x * s1 + a1.y * c1);
            a0 = n0; a1 = n1;
        }

        // ---- RY phase B: qubits 3-k on lane bit k
        #pragma unroll
        for (int k = 0; k < 4; k++) {
            int m = 1 << k;
            float c = ryc[blk * N_Q + (3 - k)], s = rys[blk * N_Q + (3 - k)];
            float b0x = __shfl_xor_sync(0xffffffffu, a0.x, m);
            float b0y = __shfl_xor_sync(0xffffffffu, a0.y, m);
            float b1x = __shfl_xor_sync(0xffffffffu, a1.x, m);
            float b1y = __shfl_xor_sync(0xffffffffu, a1.y, m);
            float sg  = (lane & m) ? s : -s;
            ull cp = pk(c, c), sgp = pk(sg, sg);
            ull n0 = fma2_(pk(b0x, b0y), sgp, mul2_(pk(a0.x, a0.y), cp));
            ull n1 = fma2_(pk(b1x, b1y), sgp, mul2_(pk(a1.x, a1.y), cp));
            upk(n0, a0.x, a0.y); upk(n1, a1.x, a1.y);
        }

        // ---- transpose B -> A
        xb[1][widx] = make_float4(a0.x, a0.y, a1.x, a1.y);
        __syncthreads();
        {
            float4 v = xb[1][ridx];
            a0 = make_float2(v.x, v.y);
            a1 = make_float2(v.z, v.w);
        }

        // ---- RY phase A: qubit 9 local, qubits 8-k on lane bit k
        {
            float c = ryc[blk * N_Q + 9], s = rys[blk * N_Q + 9];
            ull p0 = pk(a0.x, a0.y), p1 = pk(a1.x, a1.y);
            ull cp = pk(c, c);
            ull n0 = fma2_(p1, pk(-s, -s), mul2_(p0, cp));
            ull n1 = fma2_(p1, cp, mul2_(p0, pk(s, s)));
            upk(n0, a0.x, a0.y); upk(n1, a1.x, a1.y);
        }
        #pragma unroll
        for (int k = 0; k < 5; k++) {
            int m = 1 << k;
            float c = ryc[blk * N_Q + (8 - k)], s = rys[blk * N_Q + (8 - k)];
            float b0x = __shfl_xor_sync(0xffffffffu, a0.x, m);
            float b0y = __shfl_xor_sync(0xffffffffu, a0.y, m);
            float b1x = __shfl_xor_sync(0xffffffffu, a1.x, m);
            float b1y = __shfl_xor_sync(0xffffffffu, a1.y, m);
            float sg  = (lane & m) ? s : -s;
            ull cp = pk(c, c), sgp = pk(sg, sg);
            ull n0 = fma2_(pk(b0x, b0y), sgp, mul2_(pk(a0.x, a0.y), cp));
            ull n1 = fma2_(pk(b1x, b1y), sgp, mul2_(pk(a1.x, a1.y), cp));
            upk(n0, a0.x, a0.y); upk(n1, a1.x, a1.y);
        }

        // ---- CRZ-ring diagonal (phase-A ownership)
        {
            float ang0 = 0.0f, ang1 = 0.0f;
            #pragma unroll
            for (int q = 0; q < N_Q; q++) {
                int pA = N_Q - 1 - q;
                int pB = (q == N_Q - 1) ? (N_Q - 1) : (N_Q - 2 - q);
                float cz = crz[blk * N_Q + q];
                if ((dA0 >> pA) & 1) ang0 += (((dA0 >> pB) & 1) ? 0.5f : -0.5f) * cz;
                if ((dA1 >> pA) & 1) ang1 += (((dA1 >> pB) & 1) ? 0.5f : -0.5f) * cz;
            }
            float s0, c0, s1, c1;
            __sincosf(ang0, &s0, &c0);
            __sincosf(ang1, &s1, &c1);
            float2 n0 = make_float2(a0.x * c0 - a0.y * s0, a0.x * s0 + a0.y * c0);
            float2 n1 = make_float2(a1.x * c1 - a1.y * s1, a1.x * s1 + a1.y * c1);
            a0 = n0; a1 = n1;
        }
    }

    g_psiT4[t * P + pt] = make_float4(a0.x, a0.y, a1.x, a1.y);

    grid_sync();

    // ====================== PHASE 2: symmetric Gram ======================
    {
        ull* sbuf = (ull*)&xb[0][0];         // reuse smem: 512*2 ull = 8 KB
        const int ii = t & 7;
        const int jj = (t >> 3) & 7;
        const int ks = t >> 6;               // 0..7 split-K groups

        for (int tile = blockIdx.x; tile < NTILE; tile += NBLK) {
            int I = 0, rem = tile;
            while (rem >= G - I) { rem -= G - I; I++; }
            const int J = I + rem;
            const int i = I * 8 + ii;
            const int j = J * 8 + jj;
            const float w = (I < J) ? 2.0f : ((ii < jj) ? 2.0f : 0.0f);

            ull accp = 0ull, accm = 0ull;
            const int dp0 = ks * 64;
            #pragma unroll 4
            for (int dp = dp0; dp < dp0 + 64; dp++) {
                float4 A = __ldg(&g_psiT4[dp * P + i]);
                float4 B = __ldg(&g_psiT4[dp * P + j]);
                fma2acc(accp, pk(A.x, A.y), pk(B.x, B.y));
                fma2acc(accm, pk(A.y, A.x), pk(B.x, B.y));
                fma2acc(accp, pk(A.z, A.w), pk(B.z, B.w));
                fma2acc(accm, pk(A.w, A.z), pk(B.z, B.w));
            }

            __syncthreads();                 // sbuf reuse across tiles
            sbuf[t * 2 + 0] = accp;
            sbuf[t * 2 + 1] = accm;
            __syncthreads();

            float v1 = 0.0f, v2 = 0.0f;
            if (ks == 0) {
                #pragma unroll
                for (int g = 1; g < 8; g++) {
                    add2acc(accp, sbuf[(g * 64 + t) * 2 + 0]);
                    add2acc(accm, sbuf[(g * 64 + t) * 2 + 1]);
                }
                float pxx, pyy, myx, mxy;
                upk(accp, pxx, pyy);
                upk(accm, myx, mxy);
                float re = pxx + pyy;
                float im = mxy - myx;
                float K  = re * re + im * im;
                v1 = w * labels[i] * labels[j] * K;
                v2 = w * K * K;
            }

            #pragma unroll
            for (int o = 16; o; o >>= 1) {
                v1 += __shfl_down_sync(0xffffffffu, v1, o);
                v2 += __shfl_down_sync(0xffffffffu, v2, o);
            }
            const int warp = t >> 5, lanei = t & 31;
            if (lanei == 0) { red1[warp] = v1; red2[warp] = v2; }
            __syncthreads();
            if (t < 16) {
                v1 = red1[t]; v2 = red2[t];
                #pragma unroll
                for (int o = 8; o; o >>= 1) {
                    v1 += __shfl_down_sync(0xffffu, v1, o);
                    v2 += __shfl_down_sync(0xffffu, v2, o);
                }
                if (t == 0) {
                    g_part[tile * 2 + 0] = v1;
                    g_part[tile * 2 + 1] = v2;
                }
            }
        }
    }

    grid_sync();

    // ====================== PHASE 3: final scalar (block 0) ======================
    if (blockIdx.x == 0) {
        float pol = 0.0f, k2 = 0.0f, l2 = 0.0f;
        if (t < NTILE) { pol = g_part[2 * t]; k2 = g_part[2 * t + 1]; }
        if (t < P) {
            float l = labels[t];
            l2 = l * l;
            pol += l2;            // analytic diagonal: K[i,i] = 1
            k2  += 1.0f;
        }
        #pragma unroll
        for (int o = 16; o; o >>= 1) {
            pol += __shfl_down_sync(0xffffffffu, pol, o);
            k2  += __shfl_down_sync(0xffffffffu, k2, o);
            l2  += __shfl_down_sync(0xffffffffu, l2, o);
        }
        const int warp = t >> 5, lanei = t & 31;
        __syncthreads();
        if (lanei == 0) { red1[warp] = pol; red2[warp] = k2; ((float*)xb)[warp] = l2; }
        __syncthreads();
        if (t == 0) {
            float POL = 0.0f, K2 = 0.0f, SL = 0.0f;
            #pragma unroll
            for (int wv = 0; wv < 16; wv++) {
                POL += red1[wv]; K2 += red2[wv]; SL += ((float*)xb)[wv];
            }
            out[0] = POL / (sqrtf(K2) * SL);
        }
    }
}

// ---------------------------------------------------------------------------
extern "C" void kernel_launch(void* const* d_in, const int* in_sizes, int n_in,
                              void* d_out, int out_size)
{
    const float* data   = (const float*)d_in[0];   // [128, 100]
    const float* labels = (const float*)d_in[1];   // [128]
    const float* params = (const float*)d_in[2];   // [10, 2, 10]
    float* out = (float*)d_out;

    fused_kernel<<<NBLK, 512>>>(data, labels, params, out);
}

// round 8
// speedup vs baseline: 1.9766x; 1.0651x over previous
#include <cuda_runtime.h>
#include <math.h>

#define N_Q   10
#define NB    10
#define DIM   1024
#define P     128
#define FEAT  (NB * N_Q)
#define G     16
#define NTILE 136
#define NBLK  128

typedef unsigned long long ull;

// ---------------- scratch (device globals) ----------------
__device__ float4   g_psi[P * (DIM / 2)];    // [pt][dp] : dims (2dp, 2dp+1)
__device__ float    g_part[NTILE * 2];
__device__ unsigned g_bar  = 0;              // monotonic grid barrier
__device__ unsigned g_tick = 0;              // monotonic finish ticket

// packed f32x2 helpers ------------------------------------------------------
__device__ __forceinline__ ull pk(float lo, float hi) {
    ull r; asm("mov.b64 %0, {%1,%2};" : "=l"(r) : "f"(lo), "f"(hi)); return r;
}
__device__ __forceinline__ void upk(ull v, float& lo, float& hi) {
    asm("mov.b64 {%0,%1}, %2;" : "=f"(lo), "=f"(hi) : "l"(v));
}
__device__ __forceinline__ ull mul2_(ull a, ull b) {
    ull r; asm("mul.rn.f32x2 %0,%1,%2;" : "=l"(r) : "l"(a), "l"(b)); return r;
}
__device__ __forceinline__ ull fma2_(ull a, ull b, ull c) {
    ull r; asm("fma.rn.f32x2 %0,%1,%2,%3;" : "=l"(r) : "l"(a), "l"(b), "l"(c)); return r;
}
__device__ __forceinline__ void fma2acc(ull& acc, ull a, ull b) {
    asm("fma.rn.f32x2 %0, %1, %2, %0;" : "+l"(acc) : "l"(a), "l"(b));
}
__device__ __forceinline__ void add2acc(ull& acc, ull v) {
    asm("add.rn.f32x2 %0, %0, %1;" : "+l"(acc) : "l"(v));
}

// monotonic grid barrier (replay-safe: counter never resets)
__device__ __forceinline__ void grid_sync() {
    __syncthreads();
    __threadfence();
    if (threadIdx.x == 0) {
        unsigned old = atomicAdd(&g_bar, 1u);
        unsigned target = (old / NBLK + 1u) * NBLK;
        unsigned cur;
        do {
            asm volatile("ld.acquire.gpu.u32 %0, [%1];" : "=r"(cur) : "l"(&g_bar));
        } while (cur < target);
    }
    __syncthreads();
    __threadfence();
}

// ---------------------------------------------------------------------------
__global__ __launch_bounds__(512, 1)
void fused_kernel(const float* __restrict__ data,
                  const float* __restrict__ labels,
                  const float* __restrict__ params,
                  float* __restrict__ out)
{
    // 32 KB pool: prep transpose buffers (16 KB) / gram staging (32 KB)
    __shared__ float4 pool[2048];
    __shared__ float  ryc[NB * N_Q], rys[NB * N_Q], crz[NB * N_Q];
    __shared__ float  tRZc[NB], tRZs[NB];        // sincos(th9) per block
    __shared__ float  tCZc[NB * 4], tCZs[NB * 4];// sincos(crz delta) per block x 4
    __shared__ float  red1[16], red2[16], red3[16];
    __shared__ int    s_win;

    const int t    = threadIdx.x;
    const int pt   = blockIdx.x;
    const int lane = t & 31;
    const float R2 = 0.70710678118654752440f;
    const ull  r2p = pk(R2, R2);

    // ownership transpose: swap t bits [8:5] <-> [3:0], keep bit 4
    const int swp  = (t & 0x10) | ((t & 0xF) << 5) | ((t >> 5) & 0xF);
    const int widx = t   ^ ((t   >> 5) & 0xF);
    const int ridx = swp ^ ((swp >> 5) & 0xF);
    const int dA0 = 2 * t;                      // phase-A basis index (even)
    const int dB0 = 2 * swp;                    // phase-B basis index (even)

    // ---- init tables ----
    if (t < NB * N_Q) {
        int b = t / N_Q, q = t % N_Q;
        float a = params[(b * 2 + 0) * N_Q + q];
        float sn, cs; __sincosf(0.5f * a, &sn, &cs);
        ryc[t] = cs; rys[t] = sn;
        crz[t] = params[(b * 2 + 1) * N_Q + q];
    }
    if (t >= 256 && t < 256 + NB) {             // RZ delta = th9 (per data point)
        int b = t - 256;
        float a = data[pt * FEAT + b * N_Q + 9];
        float sn, cs; __sincosf(a, &sn, &cs);
        tRZc[b] = cs; tRZs[b] = sn;
    }
    if (t >= 320 && t < 320 + NB * 4) {         // CRZ delta: (s0-0.5)*cz9 + s8*cz8
        int u = t - 320, b = u >> 2, idx = u & 3;
        float cz9 = params[(b * 2 + 1) * N_Q + 9];
        float cz8 = params[(b * 2 + 1) * N_Q + 8];
        float delta = ((idx & 2) ? 0.5f : -0.5f) * cz9 + ((idx & 1) ? cz8 : 0.0f);
        float sn, cs; __sincosf(delta, &sn, &cs);
        tCZc[u] = cs; tCZs[u] = sn;
    }
    __syncthreads();

    // ====================== PHASE 1: state prep ======================
    {
        float4* xb0 = pool;                     // transpose ping
        float4* xb1 = pool + 512;               // transpose pong
        float2 a0 = make_float2(0.0f, 0.0f);
        float2 a1 = make_float2(0.0f, 0.0f);
        const int czidx4 = (((dA0 >> 9) & 1) * 2 + ((dA0 >> 1) & 1));

        for (int blk = 0; blk < NB; blk++) {
            float th[N_Q];
            #pragma unroll
            for (int q = 0; q < N_Q; q++)
                th[q] = __ldg(&data[pt * FEAT + blk * N_Q + q]);

            // ---- hoist diagonal angles + their sincos (independent of amps) ----
            float angRZ = 0.0f;
            #pragma unroll
            for (int q = 0; q < N_Q; q++)
                angRZ += (((dB0 >> (N_Q - 1 - q)) & 1) ? 0.5f : -0.5f) * th[q];
            float sRZ, cRZ; __sincosf(angRZ, &sRZ, &cRZ);

            float angCZ = 0.0f;
            #pragma unroll
            for (int q = 0; q < N_Q; q++) {
                int pA = N_Q - 1 - q;
                int pB = (q == N_Q - 1) ? (N_Q - 1) : (N_Q - 2 - q);
                if ((dA0 >> pA) & 1)
                    angCZ += (((dA0 >> pB) & 1) ? 0.5f : -0.5f) * crz[blk * N_Q + q];
            }
            float sCZ, cCZ; __sincosf(angCZ, &sCZ, &cCZ);

            if (blk == 0) {
                a0 = make_float2(0.03125f, 0.0f);   // H^(x10)|0> uniform, phase B
                a1 = make_float2(0.03125f, 0.0f);
            } else {
                // ---- H phase A ----
                {
                    ull p0 = pk(a0.x, a0.y), p1 = pk(a1.x, a1.y);
                    ull tt = mul2_(p0, r2p);
                    ull n0 = fma2_(p1, r2p, tt);
                    ull n1 = fma2_(p1, pk(-R2, -R2), tt);
                    upk(n0, a0.x, a0.y); upk(n1, a1.x, a1.y);
                }
                #pragma unroll
                for (int k = 0; k < 5; k++) {
                    int m = 1 << k;
                    float b0x = __shfl_xor_sync(0xffffffffu, a0.x, m);
                    float b0y = __shfl_xor_sync(0xffffffffu, a0.y, m);
                    float b1x = __shfl_xor_sync(0xffffffffu, a1.x, m);
                    float b1y = __shfl_xor_sync(0xffffffffu, a1.y, m);
                    float sg  = (lane & m) ? -R2 : R2;
                    ull sgp = pk(sg, sg);
                    ull n0 = fma2_(pk(a0.x, a0.y), sgp, mul2_(pk(b0x, b0y), r2p));
                    ull n1 = fma2_(pk(a1.x, a1.y), sgp, mul2_(pk(b1x, b1y), r2p));
                    upk(n0, a0.x, a0.y); upk(n1, a1.x, a1.y);
                }
                // ---- transpose A -> B ----
                __syncthreads();
                xb0[widx] = make_float4(a0.x, a0.y, a1.x, a1.y);
                __syncthreads();
                {
                    float4 v = xb0[ridx];
                    a0 = make_float2(v.x, v.y);
                    a1 = make_float2(v.z, v.w);
                }
                // ---- H phase B (d-bits 6..9 now lane bits 0..3) ----
                #pragma unroll
                for (int k = 0; k < 4; k++) {
                    int m = 1 << k;
                    float b0x = __shfl_xor_sync(0xffffffffu, a0.x, m);
                    float b0y = __shfl_xor_sync(0xffffffffu, a0.y, m);
                    float b1x = __shfl_xor_sync(0xffffffffu, a1.x, m);
                    float b1y = __shfl_xor_sync(0xffffffffu, a1.y, m);
                    float sg  = (lane & m) ? -R2 : R2;
                    ull sgp = pk(sg, sg);
                    ull n0 = fma2_(pk(a0.x, a0.y), sgp, mul2_(pk(b0x, b0y), r2p));
                    ull n1 = fma2_(pk(a1.x, a1.y), sgp, mul2_(pk(b1x, b1y), r2p));
                    upk(n0, a0.x, a0.y); upk(n1, a1.x, a1.y);
                }
            }

            // ---- RZ diagonal (phase B): odd d via angle addition with th9 ----
            {
                float c9 = tRZc[blk], s9 = tRZs[blk];
                float s1 = sRZ * c9 + cRZ * s9;
                float c1 = cRZ * c9 - sRZ * s9;
                float2 n0 = make_float2(a0.x * cRZ - a0.y * sRZ, a0.x * sRZ + a0.y * cRZ);
                float2 n1 = make_float2(a1.x * c1  - a1.y * s1,  a1.x * s1  + a1.y * c1);
                a0 = n0; a1 = n1;
            }

            // ---- RY phase B: qubits 3-k on lane bit k ----
            #pragma unroll
            for (int k = 0; k < 4; k++) {
                int m = 1 << k;
                float c = ryc[blk * N_Q + (3 - k)], s = rys[blk * N_Q + (3 - k)];
                float b0x = __shfl_xor_sync(0xffffffffu, a0.x, m);
                float b0y = __shfl_xor_sync(0xffffffffu, a0.y, m);
                float b1x = __shfl_xor_sync(0xffffffffu, a1.x, m);
                float b1y = __shfl_xor_sync(0xffffffffu, a1.y, m);
                float sg  = (lane & m) ? s : -s;
                ull cp = pk(c, c), sgp = pk(sg, sg);
                ull n0 = fma2_(pk(b0x, b0y), sgp, mul2_(pk(a0.x, a0.y), cp));
                ull n1 = fma2_(pk(b1x, b1y), sgp, mul2_(pk(a1.x, a1.y), cp));
                upk(n0, a0.x, a0.y); upk(n1, a1.x, a1.y);
            }

            // ---- transpose B -> A ----
            __syncthreads();
            xb1[widx] = make_float4(a0.x, a0.y, a1.x, a1.y);
            __syncthreads();
            {
                float4 v = xb1[ridx];
                a0 = make_float2(v.x, v.y);
                a1 = make_float2(v.z, v.w);
            }

            // ---- RY phase A: qubit 9 local, qubits 8-k on lane bit k ----
            {
                float c = ryc[blk * N_Q + 9], s = rys[blk * N_Q + 9];
                ull p0 = pk(a0.x, a0.y), p1 = pk(a1.x, a1.y);
                ull cp = pk(c, c);
                ull n0 = fma2_(p1, pk(-s, -s), mul2_(p0, cp));
                ull n1 = fma2_(p1, cp, mul2_(p0, pk(s, s)));
                upk(n0, a0.x, a0.y); upk(n1, a1.x, a1.y);
            }
            #pragma unroll
            for (int k = 0; k < 5; k++) {
                int m = 1 << k;
                float c = ryc[blk * N_Q + (8 - k)], s = rys[blk * N_Q + (8 - k)];
                float b0x = __shfl_xor_sync(0xffffffffu, a0.x, m);
                float b0y = __shfl_xor_sync(0xffffffffu, a0.y, m);
                float b1x = __shfl_xor_sync(0xffffffffu, a1.x, m);
                float b1y = __shfl_xor_sync(0xffffffffu, a1.y, m);
                float sg  = (lane & m) ? s : -s;
                ull cp = pk(c, c), sgp = pk(sg, sg);
                ull n0 = fma2_(pk(b0x, b0y), sgp, mul2_(pk(a0.x, a0.y), cp));
                ull n1 = fma2_(pk(b1x, b1y), sgp, mul2_(pk(a1.x, a1.y), cp));
                upk(n0, a0.x, a0.y); upk(n1, a1.x, a1.y);
            }

            // ---- CRZ diagonal (phase A): odd d via angle addition table ----
            {
                float cD = tCZc[blk * 4 + czidx4], sD = tCZs[blk * 4 + czidx4];
                float s1 = sCZ * cD + cCZ * sD;
                float c1 = cCZ * cD - sCZ * sD;
                float2 n0 = make_float2(a0.x * cCZ - a0.y * sCZ, a0.x * sCZ + a0.y * cCZ);
                float2 n1 = make_float2(a1.x * c1  - a1.y * s1,  a1.x * s1  + a1.y * c1);
                a0 = n0; a1 = n1;
            }
        }

        // coalesced write: [pt][dp]
        g_psi[pt * (DIM / 2) + t] = make_float4(a0.x, a0.y, a1.x, a1.y);
    }

    grid_sync();

    // ====================== PHASE 2: staged symmetric Gram ======================
    {
        const int ii = t & 7;
        const int jj = (t >> 3) & 7;
        const int ks = t >> 6;                  // 0..7 split-K groups
        const int u_r  = t >> 6;                // staging row (0..7)
        const int u_dp = t & 63;                // staging dp-local (0..63)

        for (int tile = blockIdx.x; tile < NTILE; tile += NBLK) {
            int I = 0, rem = tile;
            while (rem >= G - I) { rem -= G - I; I++; }
            const int J = I + rem;
            const int i = I * 8 + ii;
            const int j = J * 8 + jj;
            const float w = (I < J) ? 2.0f : ((ii < jj) ? 2.0f : 0.0f);

            // staging pointers: pool = [buf][A 512 | B 512]
            ull accp = 0ull, accm = 0ull;

            // prologue: chunk 0
            float4 rA = __ldg(&g_psi[(I * 8 + u_r) * (DIM / 2) + u_dp]);
            float4 rB = __ldg(&g_psi[(J * 8 + u_r) * (DIM / 2) + u_dp]);
            __syncthreads();                    // pool free (prep / prev tile done)
            pool[      u_dp * 8 + (u_r ^ (u_dp & 7))] = rA;
            pool[512 + u_dp * 8 + (u_r ^ (u_dp & 7))] = rB;
            __syncthreads();

            #pragma unroll
            for (int c = 0; c < 8; c++) {
                const float4* sA = pool + (c & 1) * 1024;
                const float4* sB = sA + 512;
                if (c < 7) {
                    rA = __ldg(&g_psi[(I * 8 + u_r) * (DIM / 2) + (c + 1) * 64 + u_dp]);
                    rB = __ldg(&g_psi[(J * 8 + u_r) * (DIM / 2) + (c + 1) * 64 + u_dp]);
                }
                #pragma unroll
                for (int it = 0; it < 8; it++) {
                    int dpl = ks * 8 + it;
                    int k0  = dpl & 7;
                    float4 A = sA[dpl * 8 + (ii ^ k0)];
                    float4 B = sB[dpl * 8 + (jj ^ k0)];
                    fma2acc(accp, pk(A.x, A.y), pk(B.x, B.y));
                    fma2acc(accm, pk(A.x, A.y), pk(B.y, B.x));
                    fma2acc(accp, pk(A.z, A.w), pk(B.z, B.w));
                    fma2acc(accm, pk(A.z, A.w), pk(B.w, B.z));
                }
                if (c < 7) {
                    float4* dA = pool + ((c + 1) & 1) * 1024;
                    dA[      u_dp * 8 + (u_r ^ (u_dp & 7))] = rA;
                    dA[512 + u_dp * 8 + (u_r ^ (u_dp & 7))] = rB;
                }
                __syncthreads();
            }

            // cross-ks reduction through pool-as-ull
            ull* sbuf = (ull*)pool;
            sbuf[t * 2 + 0] = accp;
            sbuf[t * 2 + 1] = accm;
            __syncthreads();

            float v1 = 0.0f, v2 = 0.0f;
            if (ks == 0) {
                #pragma unroll
                for (int g = 1; g < 8; g++) {
                    add2acc(accp, sbuf[(g * 64 + t) * 2 + 0]);
                    add2acc(accm, sbuf[(g * 64 + t) * 2 + 1]);
                }
                float pxx, pyy, mxy, myx;
                upk(accp, pxx, pyy);            // (Sum AxBx, Sum AyBy)
                upk(accm, mxy, myx);            // (Sum AxBy, Sum AyBx)
                float re = pxx + pyy;
                float im = myx - mxy;           // sign irrelevant (squared)
                float K  = re * re + im * im;
                v1 = w * labels[i] * labels[j] * K;
                v2 = w * K * K;
            }

            #pragma unroll
            for (int o = 16; o; o >>= 1) {
                v1 += __shfl_down_sync(0xffffffffu, v1, o);
                v2 += __shfl_down_sync(0xffffffffu, v2, o);
            }
            const int warp = t >> 5, lanei = t & 31;
            if (lanei == 0) { red1[warp] = v1; red2[warp] = v2; }
            __syncthreads();
            if (t < 16) {
                v1 = red1[t]; v2 = red2[t];
                #pragma unroll
                for (int o = 8; o; o >>= 1) {
                    v1 += __shfl_down_sync(0xffffu, v1, o);
                    v2 += __shfl_down_sync(0xffffu, v2, o);
                }
                if (t == 0) {
                    g_part[tile * 2 + 0] = v1;
                    g_part[tile * 2 + 1] = v2;
                }
            }
            __syncthreads();                    // red/pool reuse safety
        }
    }

    // ====================== PHASE 3: last-block-out final ======================
    if (t == 0) {
        __threadfence();
        unsigned old = atomicAdd(&g_tick, 1u);
        s_win = ((old % NBLK) == (NBLK - 1)) ? 1 : 0;
    }
    __syncthreads();

    if (s_win) {
        __threadfence();
        volatile float* vp = (volatile float*)g_part;
        float pol = 0.0f, k2 = 0.0f, l2 = 0.0f;
        if (t < NTILE) { pol = vp[2 * t]; k2 = vp[2 * t + 1]; }
        if (t < P) {
            float l = labels[t];
            l2 = l * l;
            pol += l2;                          // analytic diagonal K[i,i]=1
            k2  += 1.0f;
        }
        #pragma unroll
        for (int o = 16; o; o >>= 1) {
            pol += __shfl_down_sync(0xffffffffu, pol, o);
            k2  += __shfl_down_sync(0xffffffffu, k2, o);
            l2  += __shfl_down_sync(0xffffffffu, l2, o);
        }
        const int warp = t >> 5, lanei = t & 31;
        if (lanei == 0) { red1[warp] = pol; red2[warp] = k2; red3[warp] = l2; }
        __syncthreads();
        if (t == 0) {
            float POL = 0.0f, K2 = 0.0f, SL = 0.0f;
            #pragma unroll
            for (int wv = 0; wv < 16; wv++) {
                POL += red1[wv]; K2 += red2[wv]; SL += red3[wv];
            }
            out[0] = POL / (sqrtf(K2) * SL);
        }
    }
}

// ---------------------------------------------------------------------------
extern "C" void kernel_launch(void* const* d_in, const int* in_sizes, int n_in,
                              void* d_out, int out_size)
{
    const float* data   = (const float*)d_in[0];   // [128, 100]
    const float* labels = (const float*)d_in[1];   // [128]
    const float* params = (const float*)d_in[2];   // [10, 2, 10]
    float* out = (float*)d_out;

    fused_kernel<<<NBLK, 512>>>(data, labels, params, out);
}

// round 9
// speedup vs baseline: 2.8871x; 1.4606x over previous
#include <cuda_runtime.h>
#include <math.h>

#define N_Q   10
#define NB    10
#define DIM   1024
#define P     128
#define FEAT  (NB * N_Q)
#define NBLK  128

typedef unsigned long long ull;

// ---------------- scratch (device globals) ----------------
__device__ float4   g_psi[P * (DIM / 2)];    // [pt][dp] : dims (2dp, 2dp+1)
__device__ float    g_part[NBLK * 2];
__device__ unsigned g_bar  = 0;              // monotonic grid barrier
__device__ unsigned g_tick = 0;              // monotonic finish ticket

// packed f32x2 helpers (gram accumulators) ----------------------------------
__device__ __forceinline__ ull pk(float lo, float hi) {
    ull r; asm("mov.b64 %0, {%1,%2};" : "=l"(r) : "f"(lo), "f"(hi)); return r;
}
__device__ __forceinline__ void upk(ull v, float& lo, float& hi) {
    asm("mov.b64 {%0,%1}, %2;" : "=f"(lo), "=f"(hi) : "l"(v));
}
__device__ __forceinline__ void fma2acc(ull& acc, ull a, ull b) {
    asm("fma.rn.f32x2 %0, %1, %2, %0;" : "+l"(acc) : "l"(a), "l"(b));
}
__device__ __forceinline__ void add2acc(ull& acc, ull v) {
    asm("add.rn.f32x2 %0, %0, %1;" : "+l"(acc) : "l"(v));
}

// monotonic grid barrier (replay-safe)
__device__ __forceinline__ void grid_sync() {
    __syncthreads();
    __threadfence();
    if (threadIdx.x == 0) {
        unsigned old = atomicAdd(&g_bar, 1u);
        unsigned target = (old / NBLK + 1u) * NBLK;
        unsigned cur;
        do {
            asm volatile("ld.acquire.gpu.u32 %0, [%1];" : "=r"(cur) : "l"(&g_bar));
        } while (cur < target);
    }
    __syncthreads();
    __threadfence();
}

// general complex-2x2 shuffle butterfly: own' = cu*own + cv*partner
__device__ __forceinline__ void bfly(float2& a0, float2& a1, int m,
                                     const float* U8, int bit)
{
    float p0x = __shfl_xor_sync(0xffffffffu, a0.x, m);
    float p0y = __shfl_xor_sync(0xffffffffu, a0.y, m);
    float p1x = __shfl_xor_sync(0xffffffffu, a1.x, m);
    float p1y = __shfl_xor_sync(0xffffffffu, a1.y, m);
    float4 cf = *(const float4*)(U8 + (bit ? 4 : 0));  // (cu.x,cu.y,cv.x,cv.y)
    float n0x = fmaf(cf.x, a0.x, fmaf(-cf.y, a0.y, fmaf(cf.z, p0x, -cf.w * p0y)));
    float n0y = fmaf(cf.x, a0.y, fmaf( cf.y, a0.x, fmaf(cf.z, p0y,  cf.w * p0x)));
    float n1x = fmaf(cf.x, a1.x, fmaf(-cf.y, a1.y, fmaf(cf.z, p1x, -cf.w * p1y)));
    float n1y = fmaf(cf.x, a1.y, fmaf( cf.y, a1.x, fmaf(cf.z, p1y,  cf.w * p1x)));
    a0 = make_float2(n0x, n0y); a1 = make_float2(n1x, n1y);
}

// register-local butterfly on d-bit0 (qubit 9)
__device__ __forceinline__ void bflyLocal(float2& a0, float2& a1, const float* U8)
{
    float4 lo = *(const float4*)(U8);      // (u00, u01)
    float4 hi = *(const float4*)(U8 + 4);  // (u11, u10)
    float n0x = fmaf(lo.x, a0.x, fmaf(-lo.y, a0.y, fmaf(lo.z, a1.x, -lo.w * a1.y)));
    float n0y = fmaf(lo.x, a0.y, fmaf( lo.y, a0.x, fmaf(lo.z, a1.y,  lo.w * a1.x)));
    float n1x = fmaf(hi.z, a0.x, fmaf(-hi.w, a0.y, fmaf(hi.x, a1.x, -hi.y * a1.y)));
    float n1y = fmaf(hi.z, a0.y, fmaf( hi.w, a0.x, fmaf(hi.x, a1.y,  hi.y * a1.x)));
    a0 = make_float2(n0x, n0y); a1 = make_float2(n1x, n1y);
}

// ---------------------------------------------------------------------------
__global__ __launch_bounds__(512, 1)
void fused_kernel(const float* __restrict__ data,
                  const float* __restrict__ labels,
                  const float* __restrict__ params,
                  float* __restrict__ out)
{
    __shared__ float4 pool[2048];                 // 32 KB: transpose / gram staging
    __shared__ float  Umat[NB * N_Q * 8];         // folded U = RY*RZ*H per (blk,q)
    __shared__ float  crz[NB * N_Q];
    __shared__ float  tCZc[NB * 4], tCZs[NB * 4]; // CRZ odd-d delta sincos
    __shared__ float  red1[16], red2[16], red3[16];
    __shared__ int    s_win;

    const int t  = threadIdx.x;
    const int pt = blockIdx.x;

    // ownership transpose: swap t bits [8:5] <-> [3:0], keep bit 4
    const int swp  = (t & 0x10) | ((t & 0xF) << 5) | ((t >> 5) & 0xF);
    const int widx = t   ^ ((t   >> 5) & 0xF);
    const int ridx = swp ^ ((swp >> 5) & 0xF);
    const int dA0 = 2 * t;
    const int dB0 = 2 * swp;
    const int czA = (((dA0 >> 9) & 1) << 1) | ((dA0 >> 1) & 1);
    const int czB = (((dB0 >> 9) & 1) << 1) | ((dB0 >> 1) & 1);

    // ---- init: folded U matrices (per point!) + CRZ tables ----
    if (t < NB * N_Q) {
        int b = t / N_Q, q = t % N_Q;
        float th    = data[pt * FEAT + b * N_Q + q];
        float theta = params[(b * 2 + 0) * N_Q + q];
        float c, s;   __sincosf(0.5f * theta, &s, &c);
        float st, ct; __sincosf(0.5f * th, &st, &ct);
        const float iv = 0.70710678118654752440f;
        float cps = (c + s) * iv, cms = (c - s) * iv;
        float* Up = &Umat[t * 8];
        Up[0] =  cms * ct; Up[1] = -cps * st;    // u00
        Up[2] =  cps * ct; Up[3] = -cms * st;    // u01
        Up[4] = -cms * ct; Up[5] = -cps * st;    // u11
        Up[6] =  cps * ct; Up[7] =  cms * st;    // u10
        crz[t] = params[(b * 2 + 1) * N_Q + q];
    }
    if (t >= 256 && t < 256 + NB * 4) {
        int u = t - 256, b = u >> 2, idx = u & 3;
        float cz9 = params[(b * 2 + 1) * N_Q + 9];
        float cz8 = params[(b * 2 + 1) * N_Q + 8];
        float delta = ((idx & 2) ? 0.5f : -0.5f) * cz9 + ((idx & 1) ? cz8 : 0.0f);
        float sn, cs; __sincosf(delta, &sn, &cs);
        tCZc[u] = cs; tCZs[u] = sn;
    }
    __syncthreads();

    // ====================== PHASE 1: state prep ======================
    {
        float2 a0, a1;
        int tb = 0;

        // CRZ diagonal applier (even d = d0; odd via delta table)
        auto crzApply = [&](int blk, int d0, int czidx) {
            float ang = 0.0f;
            #pragma unroll
            for (int q = 0; q < N_Q; q++) {
                int pA = N_Q - 1 - q;
                int pB = (q == N_Q - 1) ? (N_Q - 1) : (N_Q - 2 - q);
                if ((d0 >> pA) & 1)
                    ang += (((d0 >> pB) & 1) ? 0.5f : -0.5f) * crz[blk * N_Q + q];
            }
            float s0, c0; __sincosf(ang, &s0, &c0);
            float cD = tCZc[blk * 4 + czidx], sD = tCZs[blk * 4 + czidx];
            float s1 = s0 * cD + c0 * sD;
            float c1 = c0 * cD - s0 * sD;
            float2 n0 = make_float2(a0.x * c0 - a0.y * s0, a0.x * s0 + a0.y * c0);
            float2 n1 = make_float2(a1.x * c1 - a1.y * s1, a1.x * s1 + a1.y * c1);
            a0 = n0; a1 = n1;
        };

        auto transpose = [&]() {
            float4* buf = pool + tb * 512;
            buf[widx] = make_float4(a0.x, a0.y, a1.x, a1.y);
            __syncthreads();
            float4 v = buf[ridx];
            a0 = make_float2(v.x, v.y);
            a1 = make_float2(v.z, v.w);
            tb ^= 1;
        };

        // state in A: apply all 10 qubit-U's then CRZ; ends in B
        auto oddPattern = [&](int blk) {
            const float* Ub = &Umat[blk * N_Q * 8];
            bflyLocal(a0, a1, Ub + 9 * 8);                       // q9 (d bit0)
            #pragma unroll
            for (int k = 0; k < 5; k++)                          // q8..q4 (d bits1-5)
                bfly(a0, a1, 1 << k, Ub + (8 - k) * 8, (t >> k) & 1);
            transpose();                                         // A -> B
            #pragma unroll
            for (int k = 0; k < 4; k++)                          // q3..q0 (d bits6-9)
                bfly(a0, a1, 1 << k, Ub + (3 - k) * 8, (t >> k) & 1);
            crzApply(blk, dB0, czB);
        };

        // state in B: ends in A
        auto evenPattern = [&](int blk) {
            const float* Ub = &Umat[blk * N_Q * 8];
            bflyLocal(a0, a1, Ub + 9 * 8);                       // q9
            #pragma unroll
            for (int k = 0; k < 4; k++)                          // q3..q0
                bfly(a0, a1, 1 << k, Ub + (3 - k) * 8, (t >> k) & 1);
            bfly(a0, a1, 16, Ub + 4 * 8, (t >> 4) & 1);          // q4 (d bit5)
            transpose();                                         // B -> A
            #pragma unroll
            for (int k = 0; k < 4; k++)                          // q8..q5 (d bits1-4)
                bfly(a0, a1, 1 << k, Ub + (8 - k) * 8, (t >> k) & 1);
            crzApply(blk, dA0, czA);
        };

        // ---- block 0: product state directly in B ownership ----
        {
            float px = 1.0f, py = 0.0f;
            #pragma unroll
            for (int q = 0; q < 9; q++) {                        // q0..q8 <-> d bits 9..1
                int bit = (dB0 >> (N_Q - 1 - q)) & 1;
                const float* Up = &Umat[q * 8] + (bit ? 6 : 0);  // u10 : u00
                float ux = Up[0], uy = Up[1];
                float nx = px * ux - py * uy;
                float ny = px * uy + py * ux;
                px = nx; py = ny;
            }
            const float* U9 = &Umat[9 * 8];
            a0 = make_float2(px * U9[0] - py * U9[1], px * U9[1] + py * U9[0]); // u00
            a1 = make_float2(px * U9[6] - py * U9[7], px * U9[7] + py * U9[6]); // u10
            crzApply(0, dB0, czB);
        }

        // blocks 1..9: alternate patterns (state B -> A -> B -> ...)
        #pragma unroll
        for (int pr = 0; pr < 4; pr++) {
            evenPattern(2 * pr + 1);
            oddPattern(2 * pr + 2);
        }
        evenPattern(9);                                          // ends in A

        g_psi[pt * (DIM / 2) + t] = make_float4(a0.x, a0.y, a1.x, a1.y);
    }

    grid_sync();

    // ====================== PHASE 2: balanced symmetric Gram ======================
    {
        const int u_r  = t >> 6;          // staging row (0..7)
        const int u_dp = t & 63;          // staging dp-local
        const int ks   = t >> 6;          // split-K group

        int grp1, grp2, ii, jj, op1, op2;
        float w;
        if (blockIdx.x < 120) {           // off-diagonal tile (I < J)
            int I = 0, rem = blockIdx.x;
            while (rem >= 15 - I) { rem -= 15 - I; I++; }
            grp1 = I; grp2 = I + 1 + rem;
            ii = t & 7; jj = (t >> 3) & 7;
            op1 = 0; op2 = 1; w = 2.0f;
        } else {                          // two diagonal tiles packed in one block
            int v = blockIdx.x - 120;
            grp1 = 2 * v; grp2 = 2 * v + 1;
            int slot = t & 63;
            if (slot < 56) {
                int sel = (slot >= 28);
                int p = slot - (sel ? 28 : 0);
                int r = 0;
                while (p >= 7 - r) { p -= 7 - r; r++; }
                ii = r; jj = r + 1 + p;   // strict upper triangle
                op1 = op2 = sel; w = 2.0f;
            } else { ii = 0; jj = 0; op1 = op2 = 0; w = 0.0f; }
        }
        const int gi = (op1 ? grp2 : grp1) * 8 + ii;
        const int gj = (op2 ? grp2 : grp1) * 8 + jj;

        ull accp = 0ull, accm = 0ull;

        // prologue: stage chunk 0
        float4 rA = __ldg(&g_psi[(grp1 * 8 + u_r) * (DIM / 2) + u_dp]);
        float4 rB = __ldg(&g_psi[(grp2 * 8 + u_r) * (DIM / 2) + u_dp]);
        __syncthreads();
        pool[      u_dp * 8 + (u_r ^ (u_dp & 7))] = rA;
        pool[512 + u_dp * 8 + (u_r ^ (u_dp & 7))] = rB;
        __syncthreads();

        #pragma unroll
        for (int c = 0; c < 8; c++) {
            const float4* base = pool + (c & 1) * 1024;
            const float4* s1 = base + op1 * 512;
            const float4* s2 = base + op2 * 512;
            if (c < 7) {
                rA = __ldg(&g_psi[(grp1 * 8 + u_r) * (DIM / 2) + (c + 1) * 64 + u_dp]);
                rB = __ldg(&g_psi[(grp2 * 8 + u_r) * (DIM / 2) + (c + 1) * 64 + u_dp]);
            }
            #pragma unroll
            for (int it = 0; it < 8; it++) {
                int dpl = ks * 8 + it;
                int k0  = dpl & 7;
                float4 A = s1[dpl * 8 + (ii ^ k0)];
                float4 B = s2[dpl * 8 + (jj ^ k0)];
                fma2acc(accp, pk(A.x, A.y), pk(B.x, B.y));
                fma2acc(accm, pk(A.x, A.y), pk(B.y, B.x));
                fma2acc(accp, pk(A.z, A.w), pk(B.z, B.w));
                fma2acc(accm, pk(A.z, A.w), pk(B.w, B.z));
            }
            if (c < 7) {
                float4* dst = pool + ((c + 1) & 1) * 1024;
                dst[      u_dp * 8 + (u_r ^ (u_dp & 7))] = rA;
                dst[512 + u_dp * 8 + (u_r ^ (u_dp & 7))] = rB;
            }
            __syncthreads();
        }

        // cross-ks reduction
        ull* sbuf = (ull*)pool;
        sbuf[t * 2 + 0] = accp;
        sbuf[t * 2 + 1] = accm;
        __syncthreads();

        float v1 = 0.0f, v2 = 0.0f;
        if (ks == 0) {
            #pragma unroll
            for (int g = 1; g < 8; g++) {
                add2acc(accp, sbuf[(g * 64 + t) * 2 + 0]);
                add2acc(accm, sbuf[(g * 64 + t) * 2 + 1]);
            }
            float pxx, pyy, mxy, myx;
            upk(accp, pxx, pyy);
            upk(accm, mxy, myx);
            float re = pxx + pyy;
            float im = myx - mxy;
            float K  = re * re + im * im;
            v1 = w * labels[gi] * labels[gj] * K;
            v2 = w * K * K;
        }

        #pragma unroll
        for (int o = 16; o; o >>= 1) {
            v1 += __shfl_down_sync(0xffffffffu, v1, o);
            v2 += __shfl_down_sync(0xffffffffu, v2, o);
        }
        const int warp = t >> 5, lanei = t & 31;
        if (lanei == 0) { red1[warp] = v1; red2[warp] = v2; }
        __syncthreads();
        if (t < 16) {
            v1 = red1[t]; v2 = red2[t];
            #pragma unroll
            for (int o = 8; o; o >>= 1) {
                v1 += __shfl_down_sync(0xffffu, v1, o);
                v2 += __shfl_down_sync(0xffffu, v2, o);
            }
            if (t == 0) {
                g_part[blockIdx.x * 2 + 0] = v1;
                g_part[blockIdx.x * 2 + 1] = v2;
            }
        }
    }

    // ====================== PHASE 3: last-block final ======================
    if (t == 0) {
        __threadfence();
        unsigned old = atomicAdd(&g_tick, 1u);
        s_win = ((old % NBLK) == (NBLK - 1)) ? 1 : 0;
    }
    __syncthreads();

    if (s_win) {
        __threadfence();
        volatile float* vp = (volatile float*)g_part;
        float pol = 0.0f, k2 = 0.0f, l2 = 0.0f;
        if (t < NBLK) { pol = vp[2 * t]; k2 = vp[2 * t + 1]; }
        if (t < P) {
            float l = labels[t];
            l2 = l * l;
            pol += l2;                      // analytic diagonal K[i,i]=1
            k2  += 1.0f;
        }
        #pragma unroll
        for (int o = 16; o; o >>= 1) {
            pol += __shfl_down_sync(0xffffffffu, pol, o);
            k2  += __shfl_down_sync(0xffffffffu, k2, o);
            l2  += __shfl_down_sync(0xffffffffu, l2, o);
        }
        const int warp = t >> 5, lanei = t & 31;
        if (lanei == 0) { red1[warp] = pol; red2[warp] = k2; red3[warp] = l2; }
        __syncthreads();
        if (t == 0) {
            float POL = 0.0f, K2 = 0.0f, SL = 0.0f;
            #pragma unroll
            for (int wv = 0; wv < 16; wv++) {
                POL += red1[wv]; K2 += red2[wv]; SL += red3[wv];
            }
            out[0] = POL / (sqrtf(K2) * SL);
        }
    }
}

// ---------------------------------------------------------------------------
extern "C" void kernel_launch(void* const* d_in, const int* in_sizes, int n_in,
                              void* d_out, int out_size)
{
    const float* data   = (const float*)d_in[0];   // [128, 100]
    const float* labels = (const float*)d_in[1];   // [128]
    const float* params = (const float*)d_in[2];   // [10, 2, 10]
    float* out = (float*)d_out;

    fused_kernel<<<NBLK, 512>>>(data, labels, params, out);
}